// round 10
// baseline (speedup 1.0000x reference)
#include <cuda_runtime.h>

#define DD 64
#define HH 512
#define WW 512
#define W4 (WW / 4)
#define THRESH 0.5f

// 64 MB scratch (device global, allocation-free rule): W+H pooled volume,
// sign bit = "raw center equals its 9x9 WH-window max" flag.
__device__ float4 g_tmp[(size_t)DD * HH * W4];

#define TH1 24   // H rows per k1 block -> 32 trips
#define DSEG 32  // D outputs per thread in k2 -> 40 trips

__device__ __forceinline__ float4 vmax4(float4 a, float4 b) {
    return make_float4(fmaxf(a.x, b.x), fmaxf(a.y, b.y),
                       fmaxf(a.z, b.z), fmaxf(a.w, b.w));
}
__device__ __forceinline__ float4 vabs4(float4 a) {
    return make_float4(fabsf(a.x), fabsf(a.y), fabsf(a.z), fabsf(a.w));
}

// ---------------------------------------------------------------------------
// k1: 9-tap W max (tree) + 9-tap H max via van Herk (in-place ring suffix at
// trip%9==8, running prefix P). Output = max(S[o-4], P). Flag (whmax == raw
// center, from 4-deep delay chain) packed as sign bit via negate-select.
// IB=true: interior in H — no row bounds checks at all.
// Threshold deferred (raw >= 0 so 0-padding exact).
// ---------------------------------------------------------------------------
template <bool IB>
__global__ void __launch_bounds__(128) k_wh_t(const float4* __restrict__ in) {
    const int t  = threadIdx.x;
    // interior: h0 = 24..480 (rows 24..503, all hi in [20,507] in-range)
    // boundary: h0 = 0 or 504
    const int h0 = IB ? (TH1 + (int)blockIdx.y * TH1)
                      : ((int)blockIdx.y * (2 * (HH - TH1) - HH + TH1)); // 0 or 504
    const int d  = blockIdx.z;
    const float4* base = in    + (size_t)d * HH * W4;
    float4*       tmpb = g_tmp + (size_t)d * HH * W4;

    const float4 z4 = make_float4(0.f, 0.f, 0.f, 0.f);
    float4 ring[9];
    float4 P = z4;
    float4 c0 = z4, c1 = z4, c2 = z4, c3 = z4;   // raw-center delay chain

#pragma unroll
    for (int hh = 0; hh < TH1 + 8; hh++) {       // 32 trips, fully unrolled
        const int hi = h0 - 4 + hh;
        float4 L, M, R;
        if (IB) {
            const float4* row = base + (size_t)hi * W4;
            L = (t > 0)      ? row[t - 1] : z4;
            M = row[t];
            R = (t < W4 - 1) ? row[t + 1] : z4;
        } else {
            const bool rowok = (hi >= 0) & (hi < HH);
            const float4* row = base + (size_t)hi * W4;
            L = (rowok && t > 0)      ? row[t - 1] : z4;
            M = rowok                 ? row[t]     : z4;
            R = (rowok && t < W4 - 1) ? row[t + 1] : z4;
        }

        // 9-tap W max: a0..a11 = L.xyzw M.xyzw R.xyzw, out_i = max(a[i..i+8])
        float c  = fmaxf(fmaxf(fmaxf(L.w, M.x), fmaxf(M.y, M.z)),
                         fmaxf(M.w, R.x));       // max(a3..a8)
        float u1 = fmaxf(L.y, L.z);
        float u2 = fmaxf(R.y, R.z);
        float4 y;
        y.x = fmaxf(fmaxf(c, L.x), u1);
        y.y = fmaxf(fmaxf(c, R.y), u1);
        y.z = fmaxf(fmaxf(c, L.z), u2);
        y.w = fmaxf(fmaxf(c, R.w), u2);

        ring[hh % 9] = y;                        // static index (full unroll)
        P = (hh % 9 == 0) ? y : vmax4(P, y);     // prefix within segment

        if (hh % 9 == 8) {                       // segment end: in-place suffix
#pragma unroll
            for (int i = 7; i >= 0; i--) ring[i] = vmax4(ring[i], ring[i + 1]);
        }

        const int ho = h0 + hh - 8;              // output row (cursor-4)
        if (hh >= 8 && (IB || ho < HH)) {
            float4 m = vmax4(ring[(hh - 8) % 9], P);
            // sign-bit flag via negate-select (1 FSETP + 1 FSEL per element)
            float4 o;
            o.x = (m.x == c3.x) ? -m.x : m.x;
            o.y = (m.y == c3.y) ? -m.y : m.y;
            o.z = (m.z == c3.z) ? -m.z : m.z;
            o.w = (m.w == c3.w) ? -m.w : m.w;
            tmpb[(size_t)ho * W4 + t] = o;
        }

        c3 = c2; c2 = c1; c1 = c0; c0 = M;       // renamed under full unroll
    }
}

// ---------------------------------------------------------------------------
// k2: 9-tap D max over |tmp| via van Herk (abs folds where possible), gate =
// (M > 0.5 && M == |center| && signbit(center)). No input re-read.
// DSEG=32 -> 40 trips, halo amp 1.25x. grid: (512, 2), block 128.
// ---------------------------------------------------------------------------
__global__ void __launch_bounds__(128) k_d(float4* __restrict__ out) {
    const size_t col   = (size_t)blockIdx.x * 128 + threadIdx.x;
    const int    d0    = blockIdx.y * DSEG;
    const size_t slice = (size_t)HH * W4;

    const float4 z4 = make_float4(0.f, 0.f, 0.f, 0.f);
    float4 ring[9];
    float4 P = z4;
    float4 c0 = z4, c1 = z4, c2 = z4, c3 = z4;   // signed raw delay chain

#pragma unroll
    for (int di = 0; di < DSEG + 8; di++) {      // 40 trips, fully unrolled
        const int p = d0 + di - 4;               // cursor plane
        float4 v = z4;
        if ((unsigned)p < DD) v = g_tmp[(size_t)p * slice + col];
        float4 a = vabs4(v);

        ring[di % 9] = a;
        P = (di % 9 == 0) ? a : vmax4(P, a);

        if (di % 9 == 8) {                       // di = 8,17,26,35
#pragma unroll
            for (int i = 7; i >= 0; i--) ring[i] = vmax4(ring[i], ring[i + 1]);
        }

        const int o = di - 8;                    // output plane offset
        if (o >= 0) {
            float4 m = vmax4(ring[(di - 8) % 9], P);
            const float4 cv = c3;                // signed center plane
            float4 ov;
            ov.x = (m.x > THRESH && m.x == fabsf(cv.x) &&
                    (__float_as_uint(cv.x) & 0x80000000u)) ? m.x : 0.f;
            ov.y = (m.y > THRESH && m.y == fabsf(cv.y) &&
                    (__float_as_uint(cv.y) & 0x80000000u)) ? m.y : 0.f;
            ov.z = (m.z > THRESH && m.z == fabsf(cv.z) &&
                    (__float_as_uint(cv.z) & 0x80000000u)) ? m.z : 0.f;
            ov.w = (m.w > THRESH && m.w == fabsf(cv.w) &&
                    (__float_as_uint(cv.w) & 0x80000000u)) ? m.w : 0.f;
            out[(size_t)(d0 + o) * slice + col] = ov;
        }

        c3 = c2; c2 = c1; c1 = c0; c0 = v;
    }
}

extern "C" void kernel_launch(void* const* d_in, const int* in_sizes, int n_in,
                              void* d_out, int out_size) {
    const float4* in  = (const float4*)d_in[0];
    float4*       out = (float4*)d_out;

    // interior: h0 = 24 + by*24, by = 0..19  (rows 24..503)
    dim3 gi(1, 20, DD);                  // 1280 blocks
    k_wh_t<true><<<gi, 128>>>(in);
    // boundary: h0 = 0 (rows 0..23) and h0 = 504 (rows 504..511, guarded)
    dim3 gb(1, 2, DD);                   // 128 blocks
    k_wh_t<false><<<gb, 128>>>(in);

    dim3 g2((HH * W4) / 128, DD / DSEG); // (512, 2) = 1024 blocks
    k_d<<<g2, 128>>>(out);
}

// round 11
// speedup vs baseline: 1.2570x; 1.2570x over previous
#include <cuda_runtime.h>

#define DD 64
#define HH 512
#define WW 512
#define W4 (WW / 4)
#define THRESH 0.5f

// 64 MB scratch (device global, allocation-free rule): W+H pooled volume,
// sign bit = "raw center equals its 9x9 WH-window max" flag.
__device__ float4 g_tmp[(size_t)DD * HH * W4];

#define TH1 24   // H rows per k1 block -> 32 trips
#define DSEG 16  // D outputs per thread in k2 -> 24 trips

__device__ __forceinline__ float4 vmax4(float4 a, float4 b) {
    return make_float4(fmaxf(a.x, b.x), fmaxf(a.y, b.y),
                       fmaxf(a.z, b.z), fmaxf(a.w, b.w));
}
__device__ __forceinline__ float4 vabs4(float4 a) {
    return make_float4(fabsf(a.x), fabsf(a.y), fabsf(a.z), fabsf(a.w));
}

// ---------------------------------------------------------------------------
// k1 body: 9-tap W max (tree) + 9-tap H max via van Herk (in-place ring
// suffix at trip%9==8, running prefix P). out[o] = max(S[o-4], P).
// Flag (whmax == raw center) packed as sign bit via negate-select.
// IB=true: no H bounds checks (interior blocks). Threshold deferred.
// ---------------------------------------------------------------------------
template <bool IB>
__device__ __forceinline__ void wh_body(const float4* __restrict__ base,
                                        float4* __restrict__ tmpb,
                                        int h0, int t) {
    const float4 z4 = make_float4(0.f, 0.f, 0.f, 0.f);
    float4 ring[9];
    float4 P = z4;
    float4 c0 = z4, c1 = z4, c2 = z4, c3 = z4;   // raw-center delay chain

#pragma unroll
    for (int hh = 0; hh < TH1 + 8; hh++) {       // 32 trips, fully unrolled
        const int hi = h0 - 4 + hh;
        float4 L, M, R;
        if (IB) {
            const float4* row = base + (size_t)hi * W4;
            L = (t > 0)      ? row[t - 1] : z4;
            M = row[t];
            R = (t < W4 - 1) ? row[t + 1] : z4;
        } else {
            const bool rowok = (hi >= 0) & (hi < HH);
            const float4* row = base + (size_t)hi * W4;
            L = (rowok && t > 0)      ? row[t - 1] : z4;
            M = rowok                 ? row[t]     : z4;
            R = (rowok && t < W4 - 1) ? row[t + 1] : z4;
        }

        // 9-tap W max: a0..a11 = L.xyzw M.xyzw R.xyzw, out_i = max(a[i..i+8])
        float c  = fmaxf(fmaxf(fmaxf(L.w, M.x), fmaxf(M.y, M.z)),
                         fmaxf(M.w, R.x));       // max(a3..a8)
        float u1 = fmaxf(L.y, L.z);
        float u2 = fmaxf(R.y, R.z);
        float4 y;
        y.x = fmaxf(fmaxf(c, L.x), u1);
        y.y = fmaxf(fmaxf(c, R.y), u1);
        y.z = fmaxf(fmaxf(c, L.z), u2);
        y.w = fmaxf(fmaxf(c, R.w), u2);

        ring[hh % 9] = y;                        // static index (full unroll)
        P = (hh % 9 == 0) ? y : vmax4(P, y);     // prefix within segment

        if (hh % 9 == 8) {                       // segment end: in-place suffix
#pragma unroll
            for (int i = 7; i >= 0; i--) ring[i] = vmax4(ring[i], ring[i + 1]);
        }

        const int ho = h0 + hh - 8;              // output row (cursor-4)
        if (hh >= 8 && (IB || ho < HH)) {
            float4 m = vmax4(ring[(hh - 8) % 9], P);
            float4 o;                            // sign-bit flag: negate-select
            o.x = (m.x == c3.x) ? -m.x : m.x;
            o.y = (m.y == c3.y) ? -m.y : m.y;
            o.z = (m.z == c3.z) ? -m.z : m.z;
            o.w = (m.w == c3.w) ? -m.w : m.w;
            tmpb[(size_t)ho * W4 + t] = o;
        }

        c3 = c2; c2 = c1; c1 = c0; c0 = M;       // renamed under full unroll
    }
}

// Single launch: by 0..19 -> interior (h0 = 24+24*by, rows 24..503, all hi
// in [20,507] in-range). by 20 -> h0 = 0, by 21 -> h0 = 504 (guarded path).
__global__ void __launch_bounds__(128) k_wh(const float4* __restrict__ in) {
    const int t  = threadIdx.x;
    const int by = blockIdx.y;
    const int d  = blockIdx.z;
    const float4* base = in    + (size_t)d * HH * W4;
    float4*       tmpb = g_tmp + (size_t)d * HH * W4;

    if (by < 20) {
        wh_body<true>(base, tmpb, TH1 + by * TH1, t);
    } else {
        wh_body<false>(base, tmpb, (by == 20) ? 0 : (HH - 8), t);
    }
}

// ---------------------------------------------------------------------------
// k2 (R9-exact): 9-tap D max over |tmp| via van Herk, gate =
// (M > 0.5 && M == |center| && signbit(center)). No input re-read.
// grid: (512, 4), block 128, DSEG=16 -> 24 trips.
// ---------------------------------------------------------------------------
__global__ void __launch_bounds__(128) k_d(float4* __restrict__ out) {
    const size_t col   = (size_t)blockIdx.x * 128 + threadIdx.x;
    const int    d0    = blockIdx.y * DSEG;
    const size_t slice = (size_t)HH * W4;

    const float4 z4 = make_float4(0.f, 0.f, 0.f, 0.f);
    float4 ring[9];
    float4 P = z4;
    float4 c0 = z4, c1 = z4, c2 = z4, c3 = z4;   // signed raw delay chain

#pragma unroll
    for (int di = 0; di < DSEG + 8; di++) {      // 24 trips, fully unrolled
        const int p = d0 + di - 4;               // cursor plane
        float4 v = z4;
        if ((unsigned)p < DD) v = g_tmp[(size_t)p * slice + col];
        float4 a = vabs4(v);

        ring[di % 9] = a;
        P = (di % 9 == 0) ? a : vmax4(P, a);

        if (di % 9 == 8) {                       // di = 8, 17
#pragma unroll
            for (int i = 7; i >= 0; i--) ring[i] = vmax4(ring[i], ring[i + 1]);
        }

        const int o = di - 8;                    // output plane offset
        if (o >= 0) {
            float4 m = vmax4(ring[(di - 8) % 9], P);
            const float4 cv = c3;                // signed center plane
            float4 ov;
            ov.x = (m.x > THRESH && m.x == fabsf(cv.x) &&
                    (__float_as_uint(cv.x) & 0x80000000u)) ? m.x : 0.f;
            ov.y = (m.y > THRESH && m.y == fabsf(cv.y) &&
                    (__float_as_uint(cv.y) & 0x80000000u)) ? m.y : 0.f;
            ov.z = (m.z > THRESH && m.z == fabsf(cv.z) &&
                    (__float_as_uint(cv.z) & 0x80000000u)) ? m.z : 0.f;
            ov.w = (m.w > THRESH && m.w == fabsf(cv.w) &&
                    (__float_as_uint(cv.w) & 0x80000000u)) ? m.w : 0.f;
            out[(size_t)(d0 + o) * slice + col] = ov;
        }

        c3 = c2; c2 = c1; c1 = c0; c0 = v;
    }
}

extern "C" void kernel_launch(void* const* d_in, const int* in_sizes, int n_in,
                              void* d_out, int out_size) {
    const float4* in  = (const float4*)d_in[0];
    float4*       out = (float4*)d_out;

    dim3 g1(1, 22, DD);                  // 1408 blocks, single launch
    k_wh<<<g1, 128>>>(in);

    dim3 g2((HH * W4) / 128, DD / DSEG); // (512, 4) = 2048 blocks
    k_d<<<g2, 128>>>(out);
}

// round 12
// speedup vs baseline: 1.2620x; 1.0040x over previous
#include <cuda_runtime.h>

#define DD 64
#define HH 512
#define WW 512
#define W4 (WW / 4)
#define THRESH 0.5f

// 64 MB scratch (device global, allocation-free rule). Convention:
//   stored value = +whmax  if raw center == 9x9 WH-window max (flag set)
//                = -whmax  otherwise.
__device__ float4 g_tmp[(size_t)DD * HH * W4];

#define TH1 24   // H rows per k1 block -> 32 trips
#define DSEG 16  // D outputs per thread in k2 -> 24 trips

__device__ __forceinline__ float4 vmax4(float4 a, float4 b) {
    return make_float4(fmaxf(a.x, b.x), fmaxf(a.y, b.y),
                       fmaxf(a.z, b.z), fmaxf(a.w, b.w));
}
__device__ __forceinline__ float4 vabs4(float4 a) {
    return make_float4(fabsf(a.x), fabsf(a.y), fabsf(a.z), fabsf(a.w));
}

// ---------------------------------------------------------------------------
// k1 body: 9-tap W max (tree) + 9-tap H max via van Herk (in-place ring
// suffix at trip%9==8, running prefix P). out[o] = max(S[o-4], P).
// Center value for the flag is RE-READ from the input at emit time (L1 hit:
// same row loaded 4 trips earlier) instead of a 4-deep register delay chain.
// IB=true: no H bounds checks. Threshold deferred (raw >= 0 -> 0-pad exact).
// ---------------------------------------------------------------------------
template <bool IB>
__device__ __forceinline__ void wh_body(const float4* __restrict__ base,
                                        float4* __restrict__ tmpb,
                                        int h0, int t) {
    const float4 z4 = make_float4(0.f, 0.f, 0.f, 0.f);
    float4 ring[9];
    float4 P = z4;

#pragma unroll
    for (int hh = 0; hh < TH1 + 8; hh++) {       // 32 trips, fully unrolled
        const int hi = h0 - 4 + hh;
        float4 L, M, R;
        if (IB) {
            const float4* row = base + (size_t)hi * W4;
            L = (t > 0)      ? row[t - 1] : z4;
            M = row[t];
            R = (t < W4 - 1) ? row[t + 1] : z4;
        } else {
            const bool rowok = (hi >= 0) & (hi < HH);
            const float4* row = base + (size_t)hi * W4;
            L = (rowok && t > 0)      ? row[t - 1] : z4;
            M = rowok                 ? row[t]     : z4;
            R = (rowok && t < W4 - 1) ? row[t + 1] : z4;
        }

        // 9-tap W max: a0..a11 = L.xyzw M.xyzw R.xyzw, out_i = max(a[i..i+8])
        float c  = fmaxf(fmaxf(fmaxf(L.w, M.x), fmaxf(M.y, M.z)),
                         fmaxf(M.w, R.x));       // max(a3..a8)
        float u1 = fmaxf(L.y, L.z);
        float u2 = fmaxf(R.y, R.z);
        float4 y;
        y.x = fmaxf(fmaxf(c, L.x), u1);
        y.y = fmaxf(fmaxf(c, R.y), u1);
        y.z = fmaxf(fmaxf(c, L.z), u2);
        y.w = fmaxf(fmaxf(c, R.w), u2);

        ring[hh % 9] = y;                        // static index (full unroll)
        P = (hh % 9 == 0) ? y : vmax4(P, y);     // prefix within segment

        if (hh % 9 == 8) {                       // segment end: in-place suffix
#pragma unroll
            for (int i = 7; i >= 0; i--) ring[i] = vmax4(ring[i], ring[i + 1]);
        }

        const int ho = h0 + hh - 8;              // output row (cursor-4)
        if (hh >= 8 && (IB || ho < HH)) {
            float4 m = vmax4(ring[(hh - 8) % 9], P);
            // re-read raw center row (L1 hit; loaded 4 trips ago)
            const float4 cen = base[(size_t)ho * W4 + t];
            float4 o;                // +m if center is WH-window max, else -m
            o.x = (m.x == cen.x) ? m.x : -m.x;
            o.y = (m.y == cen.y) ? m.y : -m.y;
            o.z = (m.z == cen.z) ? m.z : -m.z;
            o.w = (m.w == cen.w) ? m.w : -m.w;
            tmpb[(size_t)ho * W4 + t] = o;
        }
    }
}

// Single launch: by 0..19 -> interior (h0 = 24+24*by, rows 24..503, all hi
// in [20,507] in-range). by 20 -> h0 = 0, by 21 -> h0 = 504 (guarded path).
__global__ void __launch_bounds__(128) k_wh(const float4* __restrict__ in) {
    const int t  = threadIdx.x;
    const int by = blockIdx.y;
    const int d  = blockIdx.z;
    const float4* base = in    + (size_t)d * HH * W4;
    float4*       tmpb = g_tmp + (size_t)d * HH * W4;

    if (by < 20) {
        wh_body<true>(base, tmpb, TH1 + by * TH1, t);
    } else {
        wh_body<false>(base, tmpb, (by == 20) ? 0 : (HH - 8), t);
    }
}

// ---------------------------------------------------------------------------
// k2: 9-tap D max over |tmp| via van Herk. Gate: out = m if (m > 0.5 &&
// cv == m) else 0, where cv = signed tmp at the center plane (re-read, L1
// hit: loaded 4 trips earlier). cv == m implies cv > 0 (flag set) AND
// |cv| == m, i.e. center is both the WH-flagged value and the D-window max.
// grid: (512, 4), block 128, DSEG=16 -> 24 trips.
// ---------------------------------------------------------------------------
__global__ void __launch_bounds__(128) k_d(float4* __restrict__ out) {
    const size_t col   = (size_t)blockIdx.x * 128 + threadIdx.x;
    const int    d0    = blockIdx.y * DSEG;
    const size_t slice = (size_t)HH * W4;

    const float4 z4 = make_float4(0.f, 0.f, 0.f, 0.f);
    float4 ring[9];
    float4 P = z4;

#pragma unroll
    for (int di = 0; di < DSEG + 8; di++) {      // 24 trips, fully unrolled
        const int p = d0 + di - 4;               // cursor plane
        float4 v = z4;
        if ((unsigned)p < DD) v = g_tmp[(size_t)p * slice + col];
        float4 a = vabs4(v);

        ring[di % 9] = a;
        P = (di % 9 == 0) ? a : vmax4(P, a);

        if (di % 9 == 8) {                       // di = 8, 17
#pragma unroll
            for (int i = 7; i >= 0; i--) ring[i] = vmax4(ring[i], ring[i + 1]);
        }

        const int o = di - 8;                    // output plane offset
        if (o >= 0) {
            float4 m = vmax4(ring[(di - 8) % 9], P);
            // re-read signed center plane (L1 hit; loaded 4 trips ago)
            const float4 cv = g_tmp[(size_t)(d0 + o) * slice + col];
            float4 ov;
            ov.x = (m.x > THRESH && cv.x == m.x) ? m.x : 0.f;
            ov.y = (m.y > THRESH && cv.y == m.y) ? m.y : 0.f;
            ov.z = (m.z > THRESH && cv.z == m.z) ? m.z : 0.f;
            ov.w = (m.w > THRESH && cv.w == m.w) ? m.w : 0.f;
            out[(size_t)(d0 + o) * slice + col] = ov;
        }
    }
}

extern "C" void kernel_launch(void* const* d_in, const int* in_sizes, int n_in,
                              void* d_out, int out_size) {
    const float4* in  = (const float4*)d_in[0];
    float4*       out = (float4*)d_out;

    dim3 g1(1, 22, DD);                  // 1408 blocks, single launch
    k_wh<<<g1, 128>>>(in);

    dim3 g2((HH * W4) / 128, DD / DSEG); // (512, 4) = 2048 blocks
    k_d<<<g2, 128>>>(out);
}